// round 17
// baseline (speedup 1.0000x reference)
#include <cuda_runtime.h>

#define BB   64
#define MM   100
#define NN   4000
#define KK   4100          // N + M (proposal_append_gt)
#define NB   1024          // priority buckets per group
#define NCLS 80
#define BATCH_PER_IMG 512
#define NUM_FG_TARGET 128
#define ST   1024          // threads per CTA
#define SIT  5             // ceil(KK / ST)
#define GQ   148           // grid size (<= SM count -> all CTAs resident)
#define PTOT (BB * KK)     // 262400 total proposals
#define TBF  0.85f         // bg candidate priority threshold (ballot-verified)

// Scratch (static __device__ — no allocation). {mv, (float)mi} per element.
// g_cnt/g_done are zero at load and restored to zero every launch.
__device__ float2 g_pk[BB * KK];
__device__ int    g_cnt[BB];
__device__ int    g_done[BB];

// ---------------------------------------------------------------------------
// Per-pair update (R9/R14-proven exact formulation, rel_err 0.0):
//   max(x,0) = 0.5*(x+|x|)  (exact; |x| is a free operand modifier)
//   inter4 = (w+|w|)*(h+|h|) = 4*inter  (exact power-of-2 scaling)
//   argmax: iou = inter/(S-inter) monotone in inter/S -> cross-multiply.
// ---------------------------------------------------------------------------
__device__ __forceinline__ void iou_upd(float gx, float gy, float gz, float gw,
                                        float S, const float4& a,
                                        float& bi4, float& bS, int& bm, int m) {
    float lx = fmaxf(gx, a.x), ly = fmaxf(gy, a.y);
    float rx = fminf(gz, a.z), ry = fminf(gw, a.w);
    float w = rx - lx, h = ry - ly;
    float aw = w + fabsf(w);
    float ah = h + fabsf(h);
    float inter4 = aw * ah;
    if (inter4 * bS > bi4 * S) { bi4 = inter4; bS = S; bm = m; }
}

__device__ __forceinline__ void iou_finish(float bi4, float bS, int bm, int gp) {
    float uni = fmaf(-0.25f, bi4, bS);      // = rnd(S - inter), bit-identical
    float2 v;
    v.x = __fdiv_rn(0.25f * bi4, uni);      // all-zero case: 0/1 = 0 (bS init 1)
    v.y = (float)bm;                         // mi in [0,100) exact in float
    g_pk[gp] = v;                            // single STG.64
}

// ---------------------------------------------------------------------------
// Fused kernel: balanced iou partition over all 148 CTAs, then the first 128
// CTAs take per-image sample roles (fg/bg) after a per-image spin handshake.
// ---------------------------------------------------------------------------
__global__ __launch_bounds__(ST, 1) void fused_kernel(const float* __restrict__ gt,
                                                      const float* __restrict__ prop,
                                                      const float* __restrict__ pri,
                                                      const void*  __restrict__ gtcls,
                                                      float* __restrict__ out) {
    const int c   = blockIdx.x;
    const int tid = threadIdx.x;

    __shared__ float4         sgt[2 * MM];     // two gt tiles (range may cross 1 image)
    __shared__ float          sarea[2 * MM];
    __shared__ float          s_pri[KK];
    __shared__ unsigned short s_list[KK];
    __shared__ int            s_cnt[NB];       // histogram, then scatter cursor
    __shared__ int            s_P[NB + 1];     // ascending exclusive prefix
    __shared__ unsigned short s_ord[BATCH_PER_IMG];
    __shared__ int            s_wsum[33];
    __shared__ int            s_nz, s_nown, s_cbg;

    // iou partition: proposals [i0, i1)
    const int i0 = (int)(((long long)c * PTOT) / GQ);
    const int i1 = (int)(((long long)(c + 1) * PTOT) / GQ);
    const int b0 = i0 / KK;
    const int b1 = (i1 - 1) / KK;              // b0 or b0+1

    const bool isSamp = (c < 2 * BB);
    const int  sb     = c >> 1;                // sample image
    const bool isbg   = (c & 1) != 0;

    if (tid == 0) { s_nz = 0; s_nown = 0; s_cbg = 0; }
    s_cnt[tid] = 0;

    // Early issue of sample-CTA prefetches (latency hidden under iou loop).
    int gw = 0;
    if (isSamp && !isbg && tid < 64)
        gw = ((const int*)gtcls)[2 * tid + 1];     // int64 detect probe
    float ppre[SIT];
    if (isSamp) {
        #pragma unroll
        for (int it = 0; it < SIT; it++) {
            int k = tid + it * ST;
            ppre[it] = (k < KK) ? pri[(size_t)sb * KK + k] : -1.f;
        }
    }

    // gt tiles for both touched images (duplicate load if b0 == b1).
    if (tid < MM) {
        float4 g = ((const float4*)gt)[b0 * MM + tid];
        sgt[tid] = g; sarea[tid] = (g.z - g.x) * (g.w - g.y);
    } else if (tid >= 256 && tid < 256 + MM) {
        int t = tid - 256;
        float4 g = ((const float4*)gt)[b1 * MM + t];
        sgt[MM + t] = g; sarea[MM + t] = (g.z - g.x) * (g.w - g.y);
    }
    __syncthreads();

    // Retire prefetches into smem (scoreboards long drained).
    if (isSamp) {
        #pragma unroll
        for (int it = 0; it < SIT; it++) {
            int k = tid + it * ST;
            if (k < KK) s_pri[k] = ppre[it];
        }
        if (!isbg && tid < 64 && gw != 0) atomicOr(&s_nz, 1);
    }

    // ---- iou main (R14 math; 2 slots/thread, 2 parity chains/slot) ----
    const int n   = i1 - i0;
    const int gp0 = i0 + tid;
    const int gp1 = gp0 + ST;
    const bool has1 = (tid < n - ST);

    const int bs0 = gp0 / KK, k0 = gp0 - bs0 * KK;
    const int t0 = (bs0 != b0) ? MM : 0;
    float4 a0 = (k0 < NN) ? ((const float4*)prop)[(size_t)bs0 * NN + k0]
                          : sgt[t0 + (k0 - NN)];
    int bs1 = bs0, k1 = 0, t1 = t0;
    float4 a1 = a0;
    if (has1) {
        bs1 = gp1 / KK; k1 = gp1 - bs1 * KK;
        t1 = (bs1 != b0) ? MM : 0;
        a1 = (k1 < NN) ? ((const float4*)prop)[(size_t)bs1 * NN + k1]
                       : sgt[t1 + (k1 - NN)];
    }
    float areaA0 = (a0.z - a0.x) * (a0.w - a0.y);
    float areaA1 = (a1.z - a1.x) * (a1.w - a1.y);

    const float4* T0 = sgt + t0;   const float* A0 = sarea + t0;
    const float4* T1 = sgt + t1;   const float* A1 = sarea + t1;

    float bi0e = 0.f, bS0e = 1.f; int bm0e = 0;
    float bi0o = 0.f, bS0o = 1.f; int bm0o = 1;
    float bi1e = 0.f, bS1e = 1.f; int bm1e = 0;
    float bi1o = 0.f, bS1o = 1.f; int bm1o = 1;

    #pragma unroll 4
    for (int m = 0; m < MM; m += 2) {
        {
            float4 g = T0[m];     float ga = A0[m];
            iou_upd(g.x, g.y, g.z, g.w, ga + areaA0, a0, bi0e, bS0e, bm0e, m);
            float4 h = T1[m];     float ha = A1[m];
            iou_upd(h.x, h.y, h.z, h.w, ha + areaA1, a1, bi1e, bS1e, bm1e, m);
        }
        {
            float4 g = T0[m + 1]; float ga = A0[m + 1];
            iou_upd(g.x, g.y, g.z, g.w, ga + areaA0, a0, bi0o, bS0o, bm0o, m + 1);
            float4 h = T1[m + 1]; float ha = A1[m + 1];
            iou_upd(h.x, h.y, h.z, h.w, ha + areaA1, a1, bi1o, bS1o, bm1o, m + 1);
        }
    }

    {
        float c0 = bi0e * bS0o, c1 = bi0o * bS0e;
        bool useE = (c0 > c1) || (c0 == c1 && bm0e < bm0o);
        iou_finish(useE ? bi0e : bi0o, useE ? bS0e : bS0o, useE ? bm0e : bm0o, gp0);
    }
    if (has1) {
        float c0 = bi1e * bS1o, c1 = bi1o * bS1e;
        bool useE = (c0 > c1) || (c0 == c1 && bm1e < bm1o);
        iou_finish(useE ? bi1e : bi1o, useE ? bS1e : bS1o, useE ? bm1e : bm1o, gp1);
    }

    // ---- signal per-image completion (release) ----
    __threadfence();
    __syncthreads();
    if (tid == 0) {
        if (b0 == b1) {
            atomicAdd(&g_cnt[b0], n);
        } else {
            int nA = (b0 + 1) * KK - i0;
            atomicAdd(&g_cnt[b0], nA);
            atomicAdd(&g_cnt[b1], n - nA);
        }
    }
    if (!isSamp) return;

    // ---- wait for image sb complete (acquire); reset handshake ----
    if (tid == 0) {
        while (atomicAdd(&g_cnt[sb], 0) != KK) { }
        __threadfence();
        int old = atomicAdd(&g_done[sb], 1);
        if (old == 1) { g_cnt[sb] = 0; g_done[sb] = 0; }   // last consumer resets
    }
    __syncthreads();

    const float2* pkb = g_pk + (size_t)sb * KK;

    // P0b: fg flags; ballot-count group size and above-threshold candidates.
    bool ov[SIT];
    unsigned nown = 0, cbg = 0;
    #pragma unroll
    for (int it = 0; it < SIT; it++) {
        int k = tid + it * ST;
        bool own = false;
        float p = -1.f;
        if (k < KK) {
            p = s_pri[k];
            bool fg = (pkb[k].x >= 0.5f);
            own = isbg ? !fg : fg;
        }
        ov[it] = own;
        unsigned m1 = __ballot_sync(0xffffffffu, own);
        unsigned m2 = __ballot_sync(0xffffffffu, own && p >= TBF);
        if ((tid & 31) == 0) { nown += __popc(m1); cbg += __popc(m2); }
    }
    if ((tid & 31) == 0) {
        if (nown) atomicAdd(&s_nown, (int)nown);
        if (cbg)  atomicAdd(&s_cbg, (int)cbg);
    }
    __syncthreads();

    // bg: threshold valid iff >= 512 bg have p >= TBF (then top-512 bg all
    // have p >= TBF; excluded are strictly lower). fg: all elements included.
    const float tbeff = (isbg && s_cbg >= BATCH_PER_IMG) ? TBF : -1e30f;

    // P1: histogram own candidates.
    short myb[SIT];
    #pragma unroll
    for (int it = 0; it < SIT; it++) {
        short bs = -1;
        if (ov[it]) {
            float p = s_pri[tid + it * ST];
            if (p >= tbeff) {
                int bk = (int)(p * (float)NB);
                bk = bk < 0 ? 0 : (bk > NB - 1 ? NB - 1 : bk);
                bs = (short)bk;
                atomicAdd(&s_cnt[bk], 1);
            }
        }
        myb[it] = bs;
    }
    __syncthreads();

    // Exclusive scan over NB=1024 counts (1 per thread).
    int v = s_cnt[tid];
    int lane = tid & 31, wid = tid >> 5;
    int incl = v;
    #pragma unroll
    for (int d = 1; d < 32; d <<= 1) {
        int nsh = __shfl_up_sync(0xffffffffu, incl, d);
        if (lane >= d) incl += nsh;
    }
    if (lane == 31) s_wsum[wid] = incl;
    __syncthreads();
    if (tid == 0) {
        int s = 0;
        #pragma unroll
        for (int i = 0; i < 32; i++) { int cc = s_wsum[i]; s_wsum[i] = s; s += cc; }
        s_wsum[32] = s;
    }
    __syncthreads();
    int ex = s_wsum[wid] + incl - v;
    s_P[tid]   = ex;
    s_cnt[tid] = ex;                    // scatter cursor
    if (tid == 0) s_P[NB] = s_wsum[32];
    __syncthreads();

    const int candTot = s_P[NB];
    const int limit   = isbg ? BATCH_PER_IMG : NUM_FG_TARGET;

    // P2: scatter candidate indices into buckets.
    #pragma unroll
    for (int it = 0; it < SIT; it++) {
        if (myb[it] >= 0) {
            int k = tid + it * ST;
            int pos = atomicAdd(&s_cnt[myb[it]], 1);
            s_list[pos] = (unsigned short)k;
        }
    }
    __syncthreads();

    // P3: exact descending rank (higher bucket = higher priority); tie-break
    // = reversed stable argsort: equal priority -> higher index first.
    #pragma unroll
    for (int it = 0; it < SIT; it++) {
        if (myb[it] >= 0) {
            int bk = myb[it];
            int lo = s_P[bk], hi = s_P[bk + 1];
            int base = candTot - hi;        // candidates in strictly-higher buckets
            if (base < limit) {
                int k = tid + it * ST;
                float p = s_pri[k];
                int r = base;
                for (int j = lo; j < hi; j++) {
                    int o = s_list[j];
                    float po = s_pri[o];
                    if (po > p || (po == p && o > k)) r++;
                }
                if (r < limit) s_ord[r] = (unsigned short)k;
            }
        }
    }
    __syncthreads();

    // Output. Both role CTAs derive num_fg from their own group count.
    const int nfg    = isbg ? (KK - s_nown) : s_nown;
    const int num_fg = nfg < NUM_FG_TARGET ? nfg : NUM_FG_TARGET;
    const int S    = BB * BATCH_PER_IMG;
    const int base = sb * BATCH_PER_IMG + tid;

    if (!isbg) {
        // fg rows [0, num_fg): always valid, mv >= 0.5 so class from gt.
        if (tid < num_fg) {
            int k  = (int)s_ord[tid];
            float2 pk = pkb[k];               // one LDG.64: {mv, mi}
            int   mi = (int)pk.y;
            int cls = (s_nz == 0) ? (int)((const long long*)gtcls)[sb * MM + mi]
                                  : ((const int*)gtcls)[sb * MM + mi];
            out[base]         = pk.x;
            out[S + base]     = (float)k;
            out[2 * S + base] = (float)cls;
            out[3 * S + base] = pk.y;
            out[4 * S + base] = 1.f;
        }
    } else {
        // bg rows [num_fg, 512) incl. invalid tail; bg class is NCLS.
        if (tid >= num_fg && tid < BATCH_PER_IMG) {
            int nbg    = KK - nfg;
            int rem    = BATCH_PER_IMG - num_fg;
            int num_bg = nbg < rem ? nbg : rem;
            int tot    = num_fg + num_bg;
            float o_iou = 0.f;
            float o_idx = -1.f, o_cls = -1.f, o_gt = -1.f, o_val = 0.f;
            if (tid < tot) {
                int k = (int)s_ord[tid - num_fg];
                float2 pk = pkb[k];           // one LDG.64: {mv, mi}
                o_iou = pk.x;
                o_idx = (float)k;
                o_cls = (float)NCLS;
                o_gt  = pk.y;
                o_val = 1.f;
            }
            out[base]         = o_iou;
            out[S + base]     = o_idx;
            out[2 * S + base] = o_cls;
            out[3 * S + base] = o_gt;
            out[4 * S + base] = o_val;
        }
    }
}

// ---------------------------------------------------------------------------
extern "C" void kernel_launch(void* const* d_in, const int* in_sizes, int n_in,
                              void* d_out, int out_size) {
    const float* gt   = (const float*)d_in[0];   // [B, M, 4]
    const float* prop = (const float*)d_in[1];   // [B, N, 4]
    const void*  gtc  = d_in[2];                 // [B, M] int64 or int32
    const float* pri  = (const float*)d_in[3];   // [B, K]
    float* out = (float*)d_out;

    fused_kernel<<<GQ, ST>>>(gt, prop, pri, gtc, out);
}